// round 5
// baseline (speedup 1.0000x reference)
#include <cuda_runtime.h>
#include <math.h>

#define G 40000
#define PP 5
#define NPIX 65536
#define ZD 32
#define FD 64
#define HD 32
#define CC 64

// ---------------- device scratch (static, allowed) ----------------
__device__ int   d_part_cnt[PP];
__device__ int   d_part_off[PP];
__device__ int   d_cursor[PP];
__device__ int   d_sorted[G];
__device__ float d_hA[G * 128];
__device__ float d_hB[G * 128];
__device__ float d_attrs[G * 11];
__device__ float d_uvmap[HD * NPIX];
__device__ float d_fA[CC * NPIX];
__device__ float d_fB[CC * NPIX];
__device__ float d_stats[2 * CC];   // sum, sumsq
__device__ float d_minv[2 * CC];    // mean, inv_std

// ---------------- part bucketing (counting sort, 5 buckets) ----------------
__global__ void k_init() {
    int t = threadIdx.x;
    if (t < PP) d_part_cnt[t] = 0;
    if (t < 2 * CC) d_stats[t] = 0.f;
}

__global__ void k_count(const int* __restrict__ gp) {
    int g = blockIdx.x * 256 + threadIdx.x;
    if (g < G) atomicAdd(&d_part_cnt[gp[g]], 1);
}

__global__ void k_offsets() {
    int o = 0;
    for (int p = 0; p < PP; p++) {
        d_part_off[p] = o;
        d_cursor[p] = o;
        o += d_part_cnt[p];
    }
}

__global__ void k_scatter(const int* __restrict__ gp) {
    int g = blockIdx.x * 256 + threadIdx.x;
    if (g < G) {
        int pos = atomicAdd(&d_cursor[gp[g]], 1);
        d_sorted[pos] = g;
    }
}

__global__ void k_zero_uv() {
    int i = blockIdx.x * 256 + threadIdx.x;
    if (i < HD * NPIX) d_uvmap[i] = 0.f;
}

// ---------------- grouped MLP GEMM: 64 gaussians x 128 outs per block ----------------
enum { MODE_H = 0, MODE_X1 = 1, MODE_X2 = 2 };

template <int DIN, int MODE, bool LEAKY>
__global__ void __launch_bounds__(256) k_mlp(
    const float* __restrict__ X,
    const float* __restrict__ Wg, int wstride,
    const float* __restrict__ Bg, int bstride,
    float* __restrict__ Y,
    const float* __restrict__ lf, const float* __restrict__ lz,
    const float* __restrict__ cx, const float* __restrict__ at)
{
    constexpr int DOUT = 128;
    constexpr int KC = 32;
    constexpr int NCH = (DIN + KC - 1) / KC;
    __shared__ __align__(16) float Xs[KC][64];
    __shared__ __align__(16) float Ws[KC][DOUT];
    __shared__ int gidx[64];

    int p = blockIdx.y;
    int cnt = d_part_cnt[p];
    int t0 = blockIdx.x * 64;
    if (t0 >= cnt) return;
    int base = d_part_off[p];
    int n = min(64, cnt - t0);
    int tid = threadIdx.x;
    if (tid < 64) gidx[tid] = d_sorted[base + t0 + min(tid, n - 1)];
    __syncthreads();

    int tx = tid & 15, ty = tid >> 4;            // 16x16 threads: 4g x 8o micro-tile
    float acc[4][8];
#pragma unroll
    for (int i = 0; i < 4; i++)
#pragma unroll
        for (int j = 0; j < 8; j++) acc[i][j] = 0.f;

    const float* Wp = Wg + (size_t)p * wstride;
    int gl = tid >> 2;
    int kk0 = (tid & 3) * 8;
    int gme = gidx[gl];

    for (int c = 0; c < NCH; c++) {
        int k0 = c * KC;
        // --- X tile (transposed into Xs[k][g]) ---
        if (MODE == MODE_H) {
            const float4* src = (const float4*)&X[gme * 128 + k0 + kk0];
            float4 a = src[0], b = src[1];
            Xs[kk0 + 0][gl] = a.x; Xs[kk0 + 1][gl] = a.y;
            Xs[kk0 + 2][gl] = a.z; Xs[kk0 + 3][gl] = a.w;
            Xs[kk0 + 4][gl] = b.x; Xs[kk0 + 5][gl] = b.y;
            Xs[kk0 + 6][gl] = b.z; Xs[kk0 + 7][gl] = b.w;
        } else {
#pragma unroll
            for (int j = 0; j < 8; j++) {
                int k = k0 + kk0 + j;
                float v = 0.f;
                if (k < FD) v = lf[p * FD + k];
                else if (k < FD + ZD) v = lz[gme * ZD + (k - FD)];
                else if (MODE == MODE_X2) {
                    if (k < FD + ZD + 3) v = cx[gme * 3 + (k - FD - ZD)];
                    else if (k < FD + ZD + 3 + 11) v = at[gme * 11 + (k - FD - ZD - 3)];
                }
                Xs[kk0 + j][gl] = v;
            }
        }
        // --- W tile ---
#pragma unroll
        for (int i = 0; i < (KC * DOUT) / 256; i++) {
            int idx = tid + i * 256;
            int k = idx >> 7;
            int o = idx & 127;
            int kg = k0 + k;
            Ws[k][o] = (kg < DIN) ? Wp[kg * DOUT + o] : 0.f;
        }
        __syncthreads();
#pragma unroll
        for (int k = 0; k < KC; k++) {
            float4 xv = *(const float4*)&Xs[k][ty * 4];
            float4 wa = *(const float4*)&Ws[k][tx * 8];
            float4 wb = *(const float4*)&Ws[k][tx * 8 + 4];
            float xr[4] = {xv.x, xv.y, xv.z, xv.w};
            float wr[8] = {wa.x, wa.y, wa.z, wa.w, wb.x, wb.y, wb.z, wb.w};
#pragma unroll
            for (int i = 0; i < 4; i++)
#pragma unroll
                for (int j = 0; j < 8; j++)
                    acc[i][j] = fmaf(xr[i], wr[j], acc[i][j]);
        }
        __syncthreads();
    }
    // epilogue
#pragma unroll
    for (int j = 0; j < 8; j++) {
        int o = tx * 8 + j;
        float b = Bg[p * bstride + o];
#pragma unroll
        for (int i = 0; i < 4; i++) {
            int gi = ty * 4 + i;
            if (gi < n) {
                float v = acc[i][j] + b;
                if (LEAKY) v = (v >= 0.f) ? v : 0.01f * v;
                Y[gidx[gi] * 128 + o] = v;
            }
        }
    }
}

// ---------------- small-output MLP layer (Dout <= 32), warp per gaussian ----------------
template <int DOUT, bool SCATTER>
__global__ void __launch_bounds__(256) k_mlp_small(
    const float* __restrict__ X,
    const float* __restrict__ Wg, int wstride,
    const float* __restrict__ Bg, int bstride,
    float* __restrict__ Y, const int* __restrict__ uvi)
{
    __shared__ float Ws[128 * 32];
    __shared__ float Bs[32];
    int p = blockIdx.y;
    int tid = threadIdx.x;
    const float* Wp = Wg + (size_t)p * wstride;
    for (int idx = tid; idx < 128 * 32; idx += 256) {
        int k = idx >> 5, o = idx & 31;
        Ws[idx] = (o < DOUT) ? Wp[k * DOUT + o] : 0.f;
    }
    if (tid < 32) Bs[tid] = (tid < DOUT) ? Bg[p * bstride + tid] : 0.f;
    int cnt = d_part_cnt[p], base = d_part_off[p];
    __syncthreads();

    int lane = tid & 31, wp = tid >> 5;
    for (int it = 0; it < 16; it++) {
        int li = blockIdx.x * 128 + it * 8 + wp;
        if (li >= cnt) break;
        int g = d_sorted[base + li];
        float hv[4];
#pragma unroll
        for (int r = 0; r < 4; r++) hv[r] = X[g * 128 + r * 32 + lane];
        float acc = Bs[lane];
#pragma unroll
        for (int k = 0; k < 128; k++) {
            float xb = __shfl_sync(0xffffffffu, hv[k >> 5], k & 31);
            acc = fmaf(xb, Ws[k * 32 + lane], acc);
        }
        if (lane < DOUT) {
            if (SCATTER) d_uvmap[lane * NPIX + uvi[g]] = acc;   // uv_idx unique -> plain store
            else Y[g * DOUT + lane] = acc;
        }
    }
}

// ---------------- direct 3x3 conv, 16x16 pixel tile, all COUT accumulators per thread ----
// INMODE: 0=none, 1=relu, 2=instnorm+relu, 3=instnorm
template <int CIN, int COUT, int INMODE, bool STATS, bool SIG>
__global__ void __launch_bounds__(256) k_conv(
    const float* __restrict__ in, const float* __restrict__ w,
    const float* __restrict__ bias, float* __restrict__ out)
{
    constexpr int KC = 8;
    __shared__ float in_s[KC][18][18];
    __shared__ __align__(16) float w_s[KC][9][COUT];
    __shared__ float wsum[8][COUT], wsum2[8][COUT];

    int tid = threadIdx.x;
    int tx = tid & 15, ty = tid >> 4;
    int x0 = blockIdx.x * 16, y0 = blockIdx.y * 16;

    float acc[COUT];
#pragma unroll
    for (int co = 0; co < COUT; co++) acc[co] = 0.f;

    for (int cc = 0; cc < CIN; cc += KC) {
        // input tile (with halo), applying the previous layer's norm/relu on load
        for (int idx = tid; idx < KC * 18 * 18; idx += 256) {
            int ci = idx / 324; int rem = idx - ci * 324;
            int yy = rem / 18, xx = rem - yy * 18;
            int gy = y0 + yy - 1, gx = x0 + xx - 1;
            float v = 0.f;
            if ((unsigned)gy < 256u && (unsigned)gx < 256u) {
                int c = cc + ci;
                v = in[c * NPIX + gy * 256 + gx];
                if (INMODE >= 2) v = (v - d_minv[c]) * d_minv[CC + c];
                if (INMODE == 1 || INMODE == 2) v = fmaxf(v, 0.f);
            }
            in_s[ci][yy][xx] = v;
        }
        // weights transposed: w_s[ci][tap][co]  (co contiguous -> float4 broadcast loads)
        for (int idx = tid; idx < KC * 9 * COUT; idx += 256) {
            int co = idx % COUT; int r = idx / COUT;
            int t = r % 9; int ci = r / 9;
            w_s[ci][t][co] = w[((size_t)co * CIN + cc + ci) * 9 + t];
        }
        __syncthreads();
#pragma unroll
        for (int ci = 0; ci < KC; ci++) {
#pragma unroll
            for (int t = 0; t < 9; t++) {
                int dy = t / 3, dx = t % 3;
                float xv = in_s[ci][ty + dy][tx + dx];
                if (COUT % 4 == 0) {
#pragma unroll
                    for (int c4 = 0; c4 < COUT / 4; c4++) {
                        float4 wv = *(const float4*)&w_s[ci][t][c4 * 4];
                        acc[c4 * 4 + 0] = fmaf(xv, wv.x, acc[c4 * 4 + 0]);
                        acc[c4 * 4 + 1] = fmaf(xv, wv.y, acc[c4 * 4 + 1]);
                        acc[c4 * 4 + 2] = fmaf(xv, wv.z, acc[c4 * 4 + 2]);
                        acc[c4 * 4 + 3] = fmaf(xv, wv.w, acc[c4 * 4 + 3]);
                    }
                } else {
#pragma unroll
                    for (int co = 0; co < COUT; co++)
                        acc[co] = fmaf(xv, w_s[ci][t][co], acc[co]);
                }
            }
        }
        __syncthreads();
    }

    int py = y0 + ty, px = x0 + tx;
#pragma unroll
    for (int co = 0; co < COUT; co++) {
        float y = acc[co] + bias[co];
        acc[co] = y;
        float o = y;
        if (SIG) o = 1.f / (1.f + expf(-y));
        out[(size_t)co * NPIX + py * 256 + px] = o;
    }

    if (STATS) {
        int lane = tid & 31, wp5 = tid >> 5;
#pragma unroll
        for (int co = 0; co < COUT; co++) {
            float s = acc[co], s2 = acc[co] * acc[co];
#pragma unroll
            for (int off = 16; off > 0; off >>= 1) {
                s += __shfl_down_sync(0xffffffffu, s, off);
                s2 += __shfl_down_sync(0xffffffffu, s2, off);
            }
            if (lane == 0) { wsum[wp5][co] = s; wsum2[wp5][co] = s2; }
        }
        __syncthreads();
        for (int co = tid; co < COUT; co += 256) {
            float s = 0.f, s2 = 0.f;
#pragma unroll
            for (int wq = 0; wq < 8; wq++) { s += wsum[wq][co]; s2 += wsum2[wq][co]; }
            atomicAdd(&d_stats[co], s);
            atomicAdd(&d_stats[CC + co], s2);
        }
    }
}

__global__ void k_finalize() {
    int c = threadIdx.x;
    if (c < CC) {
        float s = d_stats[c], s2 = d_stats[CC + c];
        float m = s * (1.f / (float)NPIX);
        float var = s2 * (1.f / (float)NPIX) - m * m;
        d_minv[c] = m;
        d_minv[CC + c] = rsqrtf(var + 1e-5f);
        d_stats[c] = 0.f;
        d_stats[CC + c] = 0.f;
    }
}

// ---------------- launch ----------------
extern "C" void kernel_launch(void* const* d_in, const int* in_sizes, int n_in,
                              void* d_out, int out_size)
{
    const float* latent_z = (const float*)d_in[0];
    const float* latent_f = (const float*)d_in[1];
    const float* cano     = (const float*)d_in[2];
    const float* m1_w_in  = (const float*)d_in[3];
    const float* m1_b_in  = (const float*)d_in[4];
    const float* m1_w_hid = (const float*)d_in[5];
    const float* m1_b_hid = (const float*)d_in[6];
    const float* m1_w_out = (const float*)d_in[7];
    const float* m1_b_out = (const float*)d_in[8];
    const float* m2_w_in  = (const float*)d_in[9];
    const float* m2_b_in  = (const float*)d_in[10];
    const float* m2_w_hid = (const float*)d_in[11];
    const float* m2_b_hid = (const float*)d_in[12];
    const float* m2_w_out = (const float*)d_in[13];
    const float* m2_b_out = (const float*)d_in[14];
    const float* cw_in    = (const float*)d_in[15];
    const float* cb_in    = (const float*)d_in[16];
    const float* cw_hid   = (const float*)d_in[17];
    const float* cb_hid   = (const float*)d_in[18];
    const float* cw_out   = (const float*)d_in[19];
    const float* cb_out   = (const float*)d_in[20];
    const int*   gs_part  = (const int*)d_in[21];
    const int*   uv_idx   = (const int*)d_in[22];
    float* out = (float*)d_out;

    // CRITICAL FIX (R3): __device__ symbols referenced from host code decay to the
    // HOST shadow address (dereferenceable via ATS on GB300 -> silent wrong data,
    // uvmap read as zeros -> sigmoid(0)=0.5 everywhere -> rel_err 0.38).
    // Resolve true device addresses via cudaGetSymbolAddress (pure query, capture-safe).
    float *hA, *hB, *attrs, *uvmap, *fA, *fB;
    cudaGetSymbolAddress((void**)&hA,    d_hA);
    cudaGetSymbolAddress((void**)&hB,    d_hB);
    cudaGetSymbolAddress((void**)&attrs, d_attrs);
    cudaGetSymbolAddress((void**)&uvmap, d_uvmap);
    cudaGetSymbolAddress((void**)&fA,    d_fA);
    cudaGetSymbolAddress((void**)&fB,    d_fB);

    // part bucketing + uvmap zeroing
    k_init<<<1, 256>>>();
    k_count<<<(G + 255) / 256, 256>>>(gs_part);
    k_offsets<<<1, 1>>>();
    k_scatter<<<(G + 255) / 256, 256>>>(gs_part);
    k_zero_uv<<<(HD * NPIX + 255) / 256, 256>>>();

    dim3 mg(625, PP);       // 625*64 = 40000 worst-case tiles per part
    dim3 sg(313, PP);       // 313*128 >= 40000

    // MLP1: 96 -> 128 -> 128 -> 128 -> 11
    k_mlp<96, MODE_X1, true><<<mg, 256>>>(nullptr, m1_w_in, 96 * 128, m1_b_in, 128,
                                          hA, latent_f, latent_z, nullptr, nullptr);
    k_mlp<128, MODE_H, true><<<mg, 256>>>(hA, m1_w_hid, 2 * 128 * 128, m1_b_hid, 2 * 128,
                                          hB, latent_f, latent_z, nullptr, nullptr);
    k_mlp<128, MODE_H, true><<<mg, 256>>>(hB, m1_w_hid + 128 * 128, 2 * 128 * 128,
                                          m1_b_hid + 128, 2 * 128,
                                          hA, latent_f, latent_z, nullptr, nullptr);
    k_mlp_small<11, false><<<sg, 256>>>(hA, m1_w_out, 128 * 11, m1_b_out, 11,
                                        attrs, nullptr);

    // MLP2: 110 -> 128 -> 128 -> 128 -> 32, scatter into uvmap
    k_mlp<110, MODE_X2, true><<<mg, 256>>>(nullptr, m2_w_in, 110 * 128, m2_b_in, 128,
                                           hB, latent_f, latent_z, cano, attrs);
    k_mlp<128, MODE_H, true><<<mg, 256>>>(hB, m2_w_hid, 2 * 128 * 128, m2_b_hid, 2 * 128,
                                          hA, latent_f, latent_z, nullptr, nullptr);
    k_mlp<128, MODE_H, true><<<mg, 256>>>(hA, m2_w_hid + 128 * 128, 2 * 128 * 128,
                                          m2_b_hid + 128, 2 * 128,
                                          hB, latent_f, latent_z, nullptr, nullptr);
    k_mlp_small<32, true><<<sg, 256>>>(hB, m2_w_out, 128 * 32, m2_b_out, 32,
                                       nullptr, uv_idx);

    // CNN: conv_in -> [relu, conv, IN] x3 -> conv_out -> sigmoid
    dim3 cg(16, 16);
    k_conv<HD, CC, 0, false, false><<<cg, 256>>>(uvmap, cw_in, cb_in, fA);
    k_conv<CC, CC, 1, true, false><<<cg, 256>>>(fA, cw_hid, cb_hid, fB);
    k_finalize<<<1, 64>>>();
    k_conv<CC, CC, 2, true, false><<<cg, 256>>>(fB, cw_hid + 64 * 64 * 9, cb_hid + 64, fA);
    k_finalize<<<1, 64>>>();
    k_conv<CC, CC, 2, true, false><<<cg, 256>>>(fA, cw_hid + 2 * 64 * 64 * 9, cb_hid + 128, fB);
    k_finalize<<<1, 64>>>();
    k_conv<CC, 3, 3, false, true><<<cg, 256>>>(fB, cw_out, cb_out, out);
}

// round 7
// speedup vs baseline: 1.0616x; 1.0616x over previous
#include <cuda_runtime.h>
#include <math.h>

#define G 40000
#define PP 5
#define NPIX 65536
#define ZD 32
#define FD 64
#define HD 32
#define CC 64

// ---------------- f32x2 packed-FMA helpers (SASS FFMA2, ptxas never emits from C++) ----
__device__ __forceinline__ unsigned long long pack2(float x, float y) {
    unsigned long long r;
    asm("mov.b64 %0, {%1, %2};" : "=l"(r) : "f"(x), "f"(y));
    return r;
}
__device__ __forceinline__ void fma2(unsigned long long& a,
                                     unsigned long long b, unsigned long long c) {
    asm("fma.rn.f32x2 %0, %1, %2, %0;" : "+l"(a) : "l"(b), "l"(c));
}
__device__ __forceinline__ float2 unpack2(unsigned long long v) {
    float2 f;
    asm("mov.b64 {%0, %1}, %2;" : "=f"(f.x), "=f"(f.y) : "l"(v));
    return f;
}

// ---------------- device scratch (static, allowed) ----------------
__device__ int   d_part_cnt[PP];
__device__ int   d_part_off[PP];
__device__ int   d_cursor[PP];
__device__ int   d_sorted[G];
__device__ float d_hA[G * 128];
__device__ float d_hB[G * 128];
__device__ float d_attrs[G * 11];
__device__ float d_uvmap[HD * NPIX];
__device__ float d_fA[CC * NPIX];
__device__ float d_fB[CC * NPIX];
__device__ float d_stats[2 * CC];   // sum, sumsq
__device__ float d_minv[2 * CC];    // mean, inv_std

// ---------------- part bucketing (counting sort, 5 buckets) ----------------
__global__ void k_init() {
    int t = threadIdx.x;
    if (t < PP) d_part_cnt[t] = 0;
    if (t < 2 * CC) d_stats[t] = 0.f;
}

__global__ void k_count(const int* __restrict__ gp) {
    int g = blockIdx.x * 256 + threadIdx.x;
    if (g < G) atomicAdd(&d_part_cnt[gp[g]], 1);
}

__global__ void k_offsets() {
    int o = 0;
    for (int p = 0; p < PP; p++) {
        d_part_off[p] = o;
        d_cursor[p] = o;
        o += d_part_cnt[p];
    }
}

__global__ void k_scatter(const int* __restrict__ gp) {
    int g = blockIdx.x * 256 + threadIdx.x;
    if (g < G) {
        int pos = atomicAdd(&d_cursor[gp[g]], 1);
        d_sorted[pos] = g;
    }
}

__global__ void k_zero_uv() {
    int i = blockIdx.x * 256 + threadIdx.x;
    if (i < HD * NPIX) d_uvmap[i] = 0.f;
}

// ---------------- grouped MLP GEMM: 64 gaussians x 128 outs per block ----------------
enum { MODE_H = 0, MODE_X1 = 1, MODE_X2 = 2 };

template <int DIN, int MODE, bool LEAKY>
__global__ void __launch_bounds__(256) k_mlp(
    const float* __restrict__ X,
    const float* __restrict__ Wg, int wstride,
    const float* __restrict__ Bg, int bstride,
    float* __restrict__ Y,
    const float* __restrict__ lf, const float* __restrict__ lz,
    const float* __restrict__ cx, const float* __restrict__ at)
{
    constexpr int DOUT = 128;
    constexpr int KC = 32;
    constexpr int NCH = (DIN + KC - 1) / KC;
    __shared__ __align__(16) float Xs[KC][64];
    __shared__ __align__(16) float Ws[KC][DOUT];
    __shared__ int gidx[64];

    int p = blockIdx.y;
    int cnt = d_part_cnt[p];
    int t0 = blockIdx.x * 64;
    if (t0 >= cnt) return;
    int base = d_part_off[p];
    int n = min(64, cnt - t0);
    int tid = threadIdx.x;
    if (tid < 64) gidx[tid] = d_sorted[base + t0 + min(tid, n - 1)];
    __syncthreads();

    int tx = tid & 15, ty = tid >> 4;            // 16x16 threads: 4g x 8o micro-tile
    // packed accumulators: acc2[i][jj] holds outputs (tx*8 + 2*jj, +1) for gaussian ty*4+i
    unsigned long long acc2[4][4];
#pragma unroll
    for (int i = 0; i < 4; i++)
#pragma unroll
        for (int j = 0; j < 4; j++) acc2[i][j] = 0ull;

    const float* Wp = Wg + (size_t)p * wstride;
    int gl = tid >> 2;
    int kk0 = (tid & 3) * 8;
    int gme = gidx[gl];

    for (int c = 0; c < NCH; c++) {
        int k0 = c * KC;
        // --- X tile (transposed into Xs[k][g]) ---
        if (MODE == MODE_H) {
            const float4* src = (const float4*)&X[gme * 128 + k0 + kk0];
            float4 a = src[0], b = src[1];
            Xs[kk0 + 0][gl] = a.x; Xs[kk0 + 1][gl] = a.y;
            Xs[kk0 + 2][gl] = a.z; Xs[kk0 + 3][gl] = a.w;
            Xs[kk0 + 4][gl] = b.x; Xs[kk0 + 5][gl] = b.y;
            Xs[kk0 + 6][gl] = b.z; Xs[kk0 + 7][gl] = b.w;
        } else {
#pragma unroll
            for (int j = 0; j < 8; j++) {
                int k = k0 + kk0 + j;
                float v = 0.f;
                if (k < FD) v = lf[p * FD + k];
                else if (k < FD + ZD) v = lz[gme * ZD + (k - FD)];
                else if (MODE == MODE_X2) {
                    if (k < FD + ZD + 3) v = cx[gme * 3 + (k - FD - ZD)];
                    else if (k < FD + ZD + 3 + 11) v = at[gme * 11 + (k - FD - ZD - 3)];
                }
                Xs[kk0 + j][gl] = v;
            }
        }
        // --- W tile ---
#pragma unroll
        for (int i = 0; i < (KC * DOUT) / 256; i++) {
            int idx = tid + i * 256;
            int k = idx >> 7;
            int o = idx & 127;
            int kg = k0 + k;
            Ws[k][o] = (kg < DIN) ? Wp[kg * DOUT + o] : 0.f;
        }
        __syncthreads();
#pragma unroll
        for (int k = 0; k < KC; k++) {
            float4 xv = *(const float4*)&Xs[k][ty * 4];
            ulonglong2 wa = *(const ulonglong2*)&Ws[k][tx * 8];
            ulonglong2 wb = *(const ulonglong2*)&Ws[k][tx * 8 + 4];
            unsigned long long xp[4] = {
                pack2(xv.x, xv.x), pack2(xv.y, xv.y),
                pack2(xv.z, xv.z), pack2(xv.w, xv.w)
            };
#pragma unroll
            for (int i = 0; i < 4; i++) {
                fma2(acc2[i][0], xp[i], wa.x);
                fma2(acc2[i][1], xp[i], wa.y);
                fma2(acc2[i][2], xp[i], wb.x);
                fma2(acc2[i][3], xp[i], wb.y);
            }
        }
        __syncthreads();
    }
    // epilogue
#pragma unroll
    for (int jj = 0; jj < 4; jj++) {
        int o0 = tx * 8 + 2 * jj;
        float b0 = Bg[p * bstride + o0];
        float b1 = Bg[p * bstride + o0 + 1];
#pragma unroll
        for (int i = 0; i < 4; i++) {
            int gi = ty * 4 + i;
            if (gi < n) {
                float2 f = unpack2(acc2[i][jj]);
                float v0 = f.x + b0;
                float v1 = f.y + b1;
                if (LEAKY) {
                    v0 = (v0 >= 0.f) ? v0 : 0.01f * v0;
                    v1 = (v1 >= 0.f) ? v1 : 0.01f * v1;
                }
                Y[gidx[gi] * 128 + o0] = v0;
                Y[gidx[gi] * 128 + o0 + 1] = v1;
            }
        }
    }
}

// ---------------- small-output MLP layer (Dout <= 32), warp per gaussian ----------------
template <int DOUT, bool SCATTER>
__global__ void __launch_bounds__(256) k_mlp_small(
    const float* __restrict__ X,
    const float* __restrict__ Wg, int wstride,
    const float* __restrict__ Bg, int bstride,
    float* __restrict__ Y, const int* __restrict__ uvi)
{
    __shared__ float Ws[128 * 32];
    __shared__ float Bs[32];
    int p = blockIdx.y;
    int tid = threadIdx.x;
    const float* Wp = Wg + (size_t)p * wstride;
    for (int idx = tid; idx < 128 * 32; idx += 256) {
        int k = idx >> 5, o = idx & 31;
        Ws[idx] = (o < DOUT) ? Wp[k * DOUT + o] : 0.f;
    }
    if (tid < 32) Bs[tid] = (tid < DOUT) ? Bg[p * bstride + tid] : 0.f;
    int cnt = d_part_cnt[p], base = d_part_off[p];
    __syncthreads();

    int lane = tid & 31, wp = tid >> 5;
    for (int it = 0; it < 16; it++) {
        int li = blockIdx.x * 128 + it * 8 + wp;
        if (li >= cnt) break;
        int g = d_sorted[base + li];
        float hv[4];
#pragma unroll
        for (int r = 0; r < 4; r++) hv[r] = X[g * 128 + r * 32 + lane];
        float acc = Bs[lane];
#pragma unroll
        for (int k = 0; k < 128; k++) {
            float xb = __shfl_sync(0xffffffffu, hv[k >> 5], k & 31);
            acc = fmaf(xb, Ws[k * 32 + lane], acc);
        }
        if (lane < DOUT) {
            if (SCATTER) d_uvmap[lane * NPIX + uvi[g]] = acc;   // uv_idx unique -> plain store
            else Y[g * DOUT + lane] = acc;
        }
    }
}

// ---------------- direct 3x3 conv, 16x16 pixel tile, all COUT accumulators per thread ----
// INMODE: 0=none, 1=relu, 2=instnorm+relu
template <int CIN, int COUT, int INMODE, bool STATS, bool SIG>
__global__ void __launch_bounds__(256) k_conv(
    const float* __restrict__ in, const float* __restrict__ w,
    const float* __restrict__ bias, float* __restrict__ out)
{
    constexpr int KC = 8;
    constexpr bool PK = (COUT % 4 == 0);
    __shared__ float in_s[KC][18][18];
    __shared__ __align__(16) float w_s[KC][9][COUT];
    __shared__ float wsum[8][COUT], wsum2[8][COUT];

    int tid = threadIdx.x;
    int tx = tid & 15, ty = tid >> 4;
    int x0 = blockIdx.x * 16, y0 = blockIdx.y * 16;

    unsigned long long acc2[PK ? COUT / 2 : 1];
    float accs[PK ? 1 : COUT];
    if (PK) {
#pragma unroll
        for (int c = 0; c < COUT / 2; c++) acc2[c] = 0ull;
    } else {
#pragma unroll
        for (int c = 0; c < COUT; c++) accs[c] = 0.f;
    }

    for (int cc = 0; cc < CIN; cc += KC) {
        // input tile (with halo), applying the previous layer's norm/relu on load
        for (int idx = tid; idx < KC * 18 * 18; idx += 256) {
            int ci = idx / 324; int rem = idx - ci * 324;
            int yy = rem / 18, xx = rem - yy * 18;
            int gy = y0 + yy - 1, gx = x0 + xx - 1;
            float v = 0.f;
            if ((unsigned)gy < 256u && (unsigned)gx < 256u) {
                int c = cc + ci;
                v = in[c * NPIX + gy * 256 + gx];
                if (INMODE >= 2) v = (v - d_minv[c]) * d_minv[CC + c];
                if (INMODE == 1 || INMODE == 2) v = fmaxf(v, 0.f);
            }
            in_s[ci][yy][xx] = v;
        }
        // weights transposed: w_s[ci][tap][co]  (co contiguous -> 128-bit broadcast loads)
        for (int idx = tid; idx < KC * 9 * COUT; idx += 256) {
            int co = idx % COUT; int r = idx / COUT;
            int t = r % 9; int ci = r / 9;
            w_s[ci][t][co] = w[((size_t)co * CIN + cc + ci) * 9 + t];
        }
        __syncthreads();
#pragma unroll
        for (int ci = 0; ci < KC; ci++) {
#pragma unroll
            for (int t = 0; t < 9; t++) {
                int dy = t / 3, dx = t % 3;
                float xv = in_s[ci][ty + dy][tx + dx];
                if (PK) {
                    unsigned long long xv2 = pack2(xv, xv);
                    const ulonglong2* wp2 = (const ulonglong2*)&w_s[ci][t][0];
#pragma unroll
                    for (int c4 = 0; c4 < COUT / 4; c4++) {
                        ulonglong2 wv = wp2[c4];
                        fma2(acc2[c4 * 2 + 0], xv2, wv.x);
                        fma2(acc2[c4 * 2 + 1], xv2, wv.y);
                    }
                } else {
#pragma unroll
                    for (int co = 0; co < COUT; co++)
                        accs[co] = fmaf(xv, w_s[ci][t][co], accs[co]);
                }
            }
        }
        __syncthreads();
    }

    int py = y0 + ty, px = x0 + tx;
    int lane = tid & 31, wp5 = tid >> 5;

    if (PK) {
#pragma unroll
        for (int c2 = 0; c2 < COUT / 2; c2++) {
            float2 f = unpack2(acc2[c2]);
            float ys[2] = { f.x + bias[2 * c2], f.y + bias[2 * c2 + 1] };
#pragma unroll
            for (int u = 0; u < 2; u++) {
                int co = 2 * c2 + u;
                float y = ys[u];
                float o = SIG ? (1.f / (1.f + expf(-y))) : y;
                out[(size_t)co * NPIX + py * 256 + px] = o;
                if (STATS) {
                    float s = y, s2 = y * y;
#pragma unroll
                    for (int off = 16; off > 0; off >>= 1) {
                        s += __shfl_down_sync(0xffffffffu, s, off);
                        s2 += __shfl_down_sync(0xffffffffu, s2, off);
                    }
                    if (lane == 0) { wsum[wp5][co] = s; wsum2[wp5][co] = s2; }
                }
            }
        }
    } else {
#pragma unroll
        for (int co = 0; co < COUT; co++) {
            float y = accs[co] + bias[co];
            float o = SIG ? (1.f / (1.f + expf(-y))) : y;
            out[(size_t)co * NPIX + py * 256 + px] = o;
            if (STATS) {
                float s = y, s2 = y * y;
#pragma unroll
                for (int off = 16; off > 0; off >>= 1) {
                    s += __shfl_down_sync(0xffffffffu, s, off);
                    s2 += __shfl_down_sync(0xffffffffu, s2, off);
                }
                if (lane == 0) { wsum[wp5][co] = s; wsum2[wp5][co] = s2; }
            }
        }
    }

    if (STATS) {
        __syncthreads();
        for (int co = tid; co < COUT; co += 256) {
            float s = 0.f, s2 = 0.f;
#pragma unroll
            for (int wq = 0; wq < 8; wq++) { s += wsum[wq][co]; s2 += wsum2[wq][co]; }
            atomicAdd(&d_stats[co], s);
            atomicAdd(&d_stats[CC + co], s2);
        }
    }
}

__global__ void k_finalize() {
    int c = threadIdx.x;
    if (c < CC) {
        float s = d_stats[c], s2 = d_stats[CC + c];
        float m = s * (1.f / (float)NPIX);
        float var = s2 * (1.f / (float)NPIX) - m * m;
        d_minv[c] = m;
        d_minv[CC + c] = rsqrtf(var + 1e-5f);
        d_stats[c] = 0.f;
        d_stats[CC + c] = 0.f;
    }
}

// ---------------- launch ----------------
extern "C" void kernel_launch(void* const* d_in, const int* in_sizes, int n_in,
                              void* d_out, int out_size)
{
    const float* latent_z = (const float*)d_in[0];
    const float* latent_f = (const float*)d_in[1];
    const float* cano     = (const float*)d_in[2];
    const float* m1_w_in  = (const float*)d_in[3];
    const float* m1_b_in  = (const float*)d_in[4];
    const float* m1_w_hid = (const float*)d_in[5];
    const float* m1_b_hid = (const float*)d_in[6];
    const float* m1_w_out = (const float*)d_in[7];
    const float* m1_b_out = (const float*)d_in[8];
    const float* m2_w_in  = (const float*)d_in[9];
    const float* m2_b_in  = (const float*)d_in[10];
    const float* m2_w_hid = (const float*)d_in[11];
    const float* m2_b_hid = (const float*)d_in[12];
    const float* m2_w_out = (const float*)d_in[13];
    const float* m2_b_out = (const float*)d_in[14];
    const float* cw_in    = (const float*)d_in[15];
    const float* cb_in    = (const float*)d_in[16];
    const float* cw_hid   = (const float*)d_in[17];
    const float* cb_hid   = (const float*)d_in[18];
    const float* cw_out   = (const float*)d_in[19];
    const float* cb_out   = (const float*)d_in[20];
    const int*   gs_part  = (const int*)d_in[21];
    const int*   uv_idx   = (const int*)d_in[22];
    float* out = (float*)d_out;

    // __device__ symbols must be resolved to true device addresses for host-side
    // argument passing (host shadow address is silently dereferenceable via ATS).
    float *hA, *hB, *attrs, *uvmap, *fA, *fB;
    cudaGetSymbolAddress((void**)&hA,    d_hA);
    cudaGetSymbolAddress((void**)&hB,    d_hB);
    cudaGetSymbolAddress((void**)&attrs, d_attrs);
    cudaGetSymbolAddress((void**)&uvmap, d_uvmap);
    cudaGetSymbolAddress((void**)&fA,    d_fA);
    cudaGetSymbolAddress((void**)&fB,    d_fB);

    // part bucketing + uvmap zeroing
    k_init<<<1, 256>>>();
    k_count<<<(G + 255) / 256, 256>>>(gs_part);
    k_offsets<<<1, 1>>>();
    k_scatter<<<(G + 255) / 256, 256>>>(gs_part);
    k_zero_uv<<<(HD * NPIX + 255) / 256, 256>>>();

    dim3 mg(625, PP);       // 625*64 = 40000 worst-case tiles per part
    dim3 sg(313, PP);       // 313*128 >= 40000

    // MLP1: 96 -> 128 -> 128 -> 128 -> 11
    k_mlp<96, MODE_X1, true><<<mg, 256>>>(nullptr, m1_w_in, 96 * 128, m1_b_in, 128,
                                          hA, latent_f, latent_z, nullptr, nullptr);
    k_mlp<128, MODE_H, true><<<mg, 256>>>(hA, m1_w_hid, 2 * 128 * 128, m1_b_hid, 2 * 128,
                                          hB, latent_f, latent_z, nullptr, nullptr);
    k_mlp<128, MODE_H, true><<<mg, 256>>>(hB, m1_w_hid + 128 * 128, 2 * 128 * 128,
                                          m1_b_hid + 128, 2 * 128,
                                          hA, latent_f, latent_z, nullptr, nullptr);
    k_mlp_small<11, false><<<sg, 256>>>(hA, m1_w_out, 128 * 11, m1_b_out, 11,
                                        attrs, nullptr);

    // MLP2: 110 -> 128 -> 128 -> 128 -> 32, scatter into uvmap
    k_mlp<110, MODE_X2, true><<<mg, 256>>>(nullptr, m2_w_in, 110 * 128, m2_b_in, 128,
                                           hB, latent_f, latent_z, cano, attrs);
    k_mlp<128, MODE_H, true><<<mg, 256>>>(hB, m2_w_hid, 2 * 128 * 128, m2_b_hid, 2 * 128,
                                          hA, latent_f, latent_z, nullptr, nullptr);
    k_mlp<128, MODE_H, true><<<mg, 256>>>(hA, m2_w_hid + 128 * 128, 2 * 128 * 128,
                                          m2_b_hid + 128, 2 * 128,
                                          hB, latent_f, latent_z, nullptr, nullptr);
    k_mlp_small<32, true><<<sg, 256>>>(hB, m2_w_out, 128 * 32, m2_b_out, 32,
                                       nullptr, uv_idx);

    // CNN: conv_in -> [relu, conv, IN] x3 -> conv_out -> sigmoid
    dim3 cg(16, 16);
    k_conv<HD, CC, 0, false, false><<<cg, 256>>>(uvmap, cw_in, cb_in, fA);
    k_conv<CC, CC, 1, true, false><<<cg, 256>>>(fA, cw_hid, cb_hid, fB);
    k_finalize<<<1, 64>>>();
    k_conv<CC, CC, 2, true, false><<<cg, 256>>>(fB, cw_hid + 64 * 64 * 9, cb_hid + 64, fA);
    k_finalize<<<1, 64>>>();
    k_conv<CC, CC, 2, true, false><<<cg, 256>>>(fA, cw_hid + 2 * 64 * 64 * 9, cb_hid + 128, fB);
    k_finalize<<<1, 64>>>();
    k_conv<CC, 3, 3, false, true><<<cg, 256>>>(fB, cw_out, cb_out, out);
}

// round 8
// speedup vs baseline: 1.3333x; 1.2559x over previous
#include <cuda_runtime.h>
#include <math.h>

#define G 40000
#define PP 5
#define NPIX 65536
#define ZD 32
#define FD 64
#define HD 32
#define CC 64

// ---------------- f32x2 packed-FMA helpers (SASS FFMA2, ptxas never emits from C++) ----
__device__ __forceinline__ unsigned long long pack2(float x, float y) {
    unsigned long long r;
    asm("mov.b64 %0, {%1, %2};" : "=l"(r) : "f"(x), "f"(y));
    return r;
}
__device__ __forceinline__ void fma2(unsigned long long& a,
                                     unsigned long long b, unsigned long long c) {
    asm("fma.rn.f32x2 %0, %1, %2, %0;" : "+l"(a) : "l"(b), "l"(c));
}
__device__ __forceinline__ float2 unpack2(unsigned long long v) {
    float2 f;
    asm("mov.b64 {%0, %1}, %2;" : "=f"(f.x), "=f"(f.y) : "l"(v));
    return f;
}

// ---------------- device scratch (static, allowed) ----------------
__device__ int   d_part_cnt[PP];
__device__ int   d_part_off[PP];
__device__ int   d_cursor[PP];
__device__ int   d_sorted[G];
__device__ float d_hA[G * 128];
__device__ float d_hB[G * 128];
__device__ float d_attrs[G * 11];
__device__ float d_uvmap[HD * NPIX];
__device__ float d_fA[CC * NPIX];
__device__ float d_fB[CC * NPIX];
__device__ float d_stats[2 * CC];   // sum, sumsq
__device__ float d_minv[2 * CC];    // mean, inv_std

// ---------------- part bucketing (counting sort, 5 buckets) ----------------
__global__ void k_init() {
    int t = threadIdx.x;
    if (t < PP) d_part_cnt[t] = 0;
    if (t < 2 * CC) d_stats[t] = 0.f;
}

__global__ void k_count(const int* __restrict__ gp) {
    int g = blockIdx.x * 256 + threadIdx.x;
    if (g < G) atomicAdd(&d_part_cnt[gp[g]], 1);
}

__global__ void k_offsets() {
    int o = 0;
    for (int p = 0; p < PP; p++) {
        d_part_off[p] = o;
        d_cursor[p] = o;
        o += d_part_cnt[p];
    }
}

__global__ void k_scatter(const int* __restrict__ gp) {
    int g = blockIdx.x * 256 + threadIdx.x;
    if (g < G) {
        int pos = atomicAdd(&d_cursor[gp[g]], 1);
        d_sorted[pos] = g;
    }
}

__global__ void k_zero_uv() {
    int i = blockIdx.x * 256 + threadIdx.x;
    if (i < HD * NPIX) d_uvmap[i] = 0.f;
}

// ---------------- grouped MLP GEMM: 64 gaussians x 128 outs per block ----------------
enum { MODE_H = 0, MODE_X1 = 1, MODE_X2 = 2 };

template <int DIN, int MODE, bool LEAKY>
__global__ void __launch_bounds__(256) k_mlp(
    const float* __restrict__ X,
    const float* __restrict__ Wg, int wstride,
    const float* __restrict__ Bg, int bstride,
    float* __restrict__ Y,
    const float* __restrict__ lf, const float* __restrict__ lz,
    const float* __restrict__ cx, const float* __restrict__ at)
{
    constexpr int DOUT = 128;
    constexpr int KC = 32;
    constexpr int NCH = (DIN + KC - 1) / KC;
    __shared__ __align__(16) float Xs[KC][64];
    __shared__ __align__(16) float Ws[KC][DOUT];
    __shared__ int gidx[64];

    int p = blockIdx.y;
    int cnt = d_part_cnt[p];
    int t0 = blockIdx.x * 64;
    if (t0 >= cnt) return;
    int base = d_part_off[p];
    int n = min(64, cnt - t0);
    int tid = threadIdx.x;
    if (tid < 64) gidx[tid] = d_sorted[base + t0 + min(tid, n - 1)];
    __syncthreads();

    int tx = tid & 15, ty = tid >> 4;            // 16x16 threads: 4g x 8o micro-tile
    unsigned long long acc2[4][4];
#pragma unroll
    for (int i = 0; i < 4; i++)
#pragma unroll
        for (int j = 0; j < 4; j++) acc2[i][j] = 0ull;

    const float* Wp = Wg + (size_t)p * wstride;
    int gl = tid >> 2;
    int kk0 = (tid & 3) * 8;
    int gme = gidx[gl];

    for (int c = 0; c < NCH; c++) {
        int k0 = c * KC;
        // --- X tile (transposed into Xs[k][g]) ---
        if (MODE == MODE_H) {
            const float4* src = (const float4*)&X[gme * 128 + k0 + kk0];
            float4 a = src[0], b = src[1];
            Xs[kk0 + 0][gl] = a.x; Xs[kk0 + 1][gl] = a.y;
            Xs[kk0 + 2][gl] = a.z; Xs[kk0 + 3][gl] = a.w;
            Xs[kk0 + 4][gl] = b.x; Xs[kk0 + 5][gl] = b.y;
            Xs[kk0 + 6][gl] = b.z; Xs[kk0 + 7][gl] = b.w;
        } else {
#pragma unroll
            for (int j = 0; j < 8; j++) {
                int k = k0 + kk0 + j;
                float v = 0.f;
                if (k < FD) v = lf[p * FD + k];
                else if (k < FD + ZD) v = lz[gme * ZD + (k - FD)];
                else if (MODE == MODE_X2) {
                    if (k < FD + ZD + 3) v = cx[gme * 3 + (k - FD - ZD)];
                    else if (k < FD + ZD + 3 + 11) v = at[gme * 11 + (k - FD - ZD - 3)];
                }
                Xs[kk0 + j][gl] = v;
            }
        }
        // --- W tile ---
#pragma unroll
        for (int i = 0; i < (KC * DOUT) / 256; i++) {
            int idx = tid + i * 256;
            int k = idx >> 7;
            int o = idx & 127;
            int kg = k0 + k;
            Ws[k][o] = (kg < DIN) ? Wp[kg * DOUT + o] : 0.f;
        }
        __syncthreads();
#pragma unroll
        for (int k = 0; k < KC; k++) {
            float4 xv = *(const float4*)&Xs[k][ty * 4];
            ulonglong2 wa = *(const ulonglong2*)&Ws[k][tx * 8];
            ulonglong2 wb = *(const ulonglong2*)&Ws[k][tx * 8 + 4];
            unsigned long long xp[4] = {
                pack2(xv.x, xv.x), pack2(xv.y, xv.y),
                pack2(xv.z, xv.z), pack2(xv.w, xv.w)
            };
#pragma unroll
            for (int i = 0; i < 4; i++) {
                fma2(acc2[i][0], xp[i], wa.x);
                fma2(acc2[i][1], xp[i], wa.y);
                fma2(acc2[i][2], xp[i], wb.x);
                fma2(acc2[i][3], xp[i], wb.y);
            }
        }
        __syncthreads();
    }
    // epilogue
#pragma unroll
    for (int jj = 0; jj < 4; jj++) {
        int o0 = tx * 8 + 2 * jj;
        float b0 = Bg[p * bstride + o0];
        float b1 = Bg[p * bstride + o0 + 1];
#pragma unroll
        for (int i = 0; i < 4; i++) {
            int gi = ty * 4 + i;
            if (gi < n) {
                float2 f = unpack2(acc2[i][jj]);
                float v0 = f.x + b0;
                float v1 = f.y + b1;
                if (LEAKY) {
                    v0 = (v0 >= 0.f) ? v0 : 0.01f * v0;
                    v1 = (v1 >= 0.f) ? v1 : 0.01f * v1;
                }
                Y[gidx[gi] * 128 + o0] = v0;
                Y[gidx[gi] * 128 + o0 + 1] = v1;
            }
        }
    }
}

// ---------------- small-output MLP layer (Dout <= 32), warp per gaussian ----------------
template <int DOUT, bool SCATTER>
__global__ void __launch_bounds__(256) k_mlp_small(
    const float* __restrict__ X,
    const float* __restrict__ Wg, int wstride,
    const float* __restrict__ Bg, int bstride,
    float* __restrict__ Y, const int* __restrict__ uvi)
{
    __shared__ float Ws[128 * 32];
    __shared__ float Bs[32];
    int p = blockIdx.y;
    int tid = threadIdx.x;
    const float* Wp = Wg + (size_t)p * wstride;
    for (int idx = tid; idx < 128 * 32; idx += 256) {
        int k = idx >> 5, o = idx & 31;
        Ws[idx] = (o < DOUT) ? Wp[k * DOUT + o] : 0.f;
    }
    if (tid < 32) Bs[tid] = (tid < DOUT) ? Bg[p * bstride + tid] : 0.f;
    int cnt = d_part_cnt[p], base = d_part_off[p];
    __syncthreads();

    int lane = tid & 31, wp = tid >> 5;
    for (int it = 0; it < 16; it++) {
        int li = blockIdx.x * 128 + it * 8 + wp;
        if (li >= cnt) break;
        int g = d_sorted[base + li];
        float hv[4];
#pragma unroll
        for (int r = 0; r < 4; r++) hv[r] = X[g * 128 + r * 32 + lane];
        float acc = Bs[lane];
#pragma unroll
        for (int k = 0; k < 128; k++) {
            float xb = __shfl_sync(0xffffffffu, hv[k >> 5], k & 31);
            acc = fmaf(xb, Ws[k * 32 + lane], acc);
        }
        if (lane < DOUT) {
            if (SCATTER) d_uvmap[lane * NPIX + uvi[g]] = acc;   // uv_idx unique -> plain store
            else Y[g * DOUT + lane] = acc;
        }
    }
}

// ---------------- NEW: 64-out direct 3x3 conv, 4px x 32co per thread, FFMA2-bound -----
// 16x16 pixel tile, 128 threads = 64 pixel-threads (4px each, x-contiguous) x 2 co-groups.
// Per tap: 4 packs (regs) + 8 broadcast LDS.128 (weights) + 64 FFMA2.
// INMODE: 0=none, 1=relu, 2=instnorm+relu (applied to input on load)
template <int CIN, int INMODE, bool STATS>
__global__ void __launch_bounds__(128, 2) k_conv64(
    const float* __restrict__ in, const float* __restrict__ w,
    const float* __restrict__ bias, float* __restrict__ out)
{
    constexpr int KC = 8;
    __shared__ float in_s[KC][18][18];
    __shared__ __align__(16) float w_s[KC][9][64];
    __shared__ float wsum[4][64], wsum2[4][64];

    int tid = threadIdx.x;
    int cg  = tid >> 6;          // co-group: 0 -> co 0..31, 1 -> co 32..63
    int pid = tid & 63;
    int ty  = pid >> 2;          // 0..15
    int txq = pid & 3;           // pixel quad: x = txq*4 + 0..3
    int x0 = blockIdx.x * 16, y0 = blockIdx.y * 16;

    unsigned long long acc2[4][16];   // [pixel][co-pair]  (64 f32x2 accumulators)
#pragma unroll
    for (int p = 0; p < 4; p++)
#pragma unroll
        for (int c = 0; c < 16; c++) acc2[p][c] = 0ull;

    for (int cc = 0; cc < CIN; cc += KC) {
        // input tile with halo; previous layer's norm/relu applied on load
        for (int idx = tid; idx < KC * 18 * 18; idx += 128) {
            int ci = idx / 324; int rem = idx - ci * 324;
            int yy = rem / 18, xx = rem - yy * 18;
            int gy = y0 + yy - 1, gx = x0 + xx - 1;
            float v = 0.f;
            if ((unsigned)gy < 256u && (unsigned)gx < 256u) {
                int c = cc + ci;
                v = in[c * NPIX + gy * 256 + gx];
                if (INMODE >= 2) v = (v - d_minv[c]) * d_minv[CC + c];
                if (INMODE >= 1) v = fmaxf(v, 0.f);
            }
            in_s[ci][yy][xx] = v;
        }
        // weights transposed: w_s[ci][tap][co] (co contiguous -> native f32x2 pairs)
        for (int idx = tid; idx < KC * 9 * 64; idx += 128) {
            int co = idx & 63; int r = idx >> 6;
            int t = r % 9; int ci = r / 9;
            w_s[ci][t][co] = w[((size_t)co * CIN + cc + ci) * 9 + t];
        }
        __syncthreads();

#pragma unroll
        for (int ci = 0; ci < KC; ci++) {
#pragma unroll
            for (int dy = 0; dy < 3; dy++) {
                // row cache: input x range [txq*4-1, txq*4+4] -> in_s cols txq*4 + 0..5
                float r[6];
#pragma unroll
                for (int j = 0; j < 6; j++) r[j] = in_s[ci][ty + dy][txq * 4 + j];
#pragma unroll
                for (int dx = 0; dx < 3; dx++) {
                    unsigned long long xd[4];
#pragma unroll
                    for (int p = 0; p < 4; p++) xd[p] = pack2(r[dx + p], r[dx + p]);
                    const ulonglong2* wp2 =
                        (const ulonglong2*)&w_s[ci][dy * 3 + dx][cg * 32];
#pragma unroll
                    for (int q = 0; q < 8; q++) {
                        ulonglong2 wv = wp2[q];
#pragma unroll
                        for (int p = 0; p < 4; p++) {
                            fma2(acc2[p][q * 2 + 0], xd[p], wv.x);
                            fma2(acc2[p][q * 2 + 1], xd[p], wv.y);
                        }
                    }
                }
            }
        }
        __syncthreads();
    }

    // epilogue: bias, store (float4 per co across the 4-px quad), warp stats
    int gy = y0 + ty;
    int gx0 = x0 + txq * 4;
    int lane = tid & 31, wid = tid >> 5;

#pragma unroll
    for (int ch = 0; ch < 16; ch++) {
        int co0 = cg * 32 + 2 * ch;
        float b0 = bias[co0], b1 = bias[co0 + 1];
        float ya[4], yb[4];
#pragma unroll
        for (int p = 0; p < 4; p++) {
            float2 f = unpack2(acc2[p][ch]);
            ya[p] = f.x + b0;
            yb[p] = f.y + b1;
        }
        *(float4*)&out[(size_t)co0 * NPIX + gy * 256 + gx0] =
            make_float4(ya[0], ya[1], ya[2], ya[3]);
        *(float4*)&out[(size_t)(co0 + 1) * NPIX + gy * 256 + gx0] =
            make_float4(yb[0], yb[1], yb[2], yb[3]);
        if (STATS) {
            float s0 = ya[0] + ya[1] + ya[2] + ya[3];
            float q0 = ya[0]*ya[0] + ya[1]*ya[1] + ya[2]*ya[2] + ya[3]*ya[3];
            float s1 = yb[0] + yb[1] + yb[2] + yb[3];
            float q1 = yb[0]*yb[0] + yb[1]*yb[1] + yb[2]*yb[2] + yb[3]*yb[3];
#pragma unroll
            for (int off = 16; off > 0; off >>= 1) {
                s0 += __shfl_down_sync(0xffffffffu, s0, off);
                q0 += __shfl_down_sync(0xffffffffu, q0, off);
                s1 += __shfl_down_sync(0xffffffffu, s1, off);
                q1 += __shfl_down_sync(0xffffffffu, q1, off);
            }
            if (lane == 0) {
                wsum[wid][co0] = s0;  wsum2[wid][co0] = q0;
                wsum[wid][co0 + 1] = s1; wsum2[wid][co0 + 1] = q1;
            }
        }
    }

    if (STATS) {
        __syncthreads();
        // warps 0-1 hold co 0..31; warps 2-3 hold co 32..63
        for (int co = tid; co < 64; co += 128) {
            int lo = (co < 32) ? 0 : 2;
            atomicAdd(&d_stats[co],      wsum[lo][co] + wsum[lo + 1][co]);
            atomicAdd(&d_stats[CC + co], wsum2[lo][co] + wsum2[lo + 1][co]);
        }
    }
}

// ---------------- small-output conv (COUT=3) with IN on load + sigmoid ----------------
template <int CIN, int COUT, int INMODE, bool SIG>
__global__ void __launch_bounds__(256) k_conv_small(
    const float* __restrict__ in, const float* __restrict__ w,
    const float* __restrict__ bias, float* __restrict__ out)
{
    constexpr int KC = 8;
    __shared__ float in_s[KC][18][18];
    __shared__ __align__(16) float w_s[KC][9][COUT];

    int tid = threadIdx.x;
    int tx = tid & 15, ty = tid >> 4;
    int x0 = blockIdx.x * 16, y0 = blockIdx.y * 16;

    float accs[COUT];
#pragma unroll
    for (int c = 0; c < COUT; c++) accs[c] = 0.f;

    for (int cc = 0; cc < CIN; cc += KC) {
        for (int idx = tid; idx < KC * 18 * 18; idx += 256) {
            int ci = idx / 324; int rem = idx - ci * 324;
            int yy = rem / 18, xx = rem - yy * 18;
            int gy = y0 + yy - 1, gx = x0 + xx - 1;
            float v = 0.f;
            if ((unsigned)gy < 256u && (unsigned)gx < 256u) {
                int c = cc + ci;
                v = in[c * NPIX + gy * 256 + gx];
                if (INMODE >= 2) v = (v - d_minv[c]) * d_minv[CC + c];
                if (INMODE == 1 || INMODE == 2) v = fmaxf(v, 0.f);
            }
            in_s[ci][yy][xx] = v;
        }
        for (int idx = tid; idx < KC * 9 * COUT; idx += 256) {
            int co = idx % COUT; int r = idx / COUT;
            int t = r % 9; int ci = r / 9;
            w_s[ci][t][co] = w[((size_t)co * CIN + cc + ci) * 9 + t];
        }
        __syncthreads();
#pragma unroll
        for (int ci = 0; ci < KC; ci++) {
#pragma unroll
            for (int t = 0; t < 9; t++) {
                int dy = t / 3, dx = t % 3;
                float xv = in_s[ci][ty + dy][tx + dx];
#pragma unroll
                for (int co = 0; co < COUT; co++)
                    accs[co] = fmaf(xv, w_s[ci][t][co], accs[co]);
            }
        }
        __syncthreads();
    }

    int py = y0 + ty, px = x0 + tx;
#pragma unroll
    for (int co = 0; co < COUT; co++) {
        float y = accs[co] + bias[co];
        float o = SIG ? (1.f / (1.f + expf(-y))) : y;
        out[(size_t)co * NPIX + py * 256 + px] = o;
    }
}

__global__ void k_finalize() {
    int c = threadIdx.x;
    if (c < CC) {
        float s = d_stats[c], s2 = d_stats[CC + c];
        float m = s * (1.f / (float)NPIX);
        float var = s2 * (1.f / (float)NPIX) - m * m;
        d_minv[c] = m;
        d_minv[CC + c] = rsqrtf(var + 1e-5f);
        d_stats[c] = 0.f;
        d_stats[CC + c] = 0.f;
    }
}

// ---------------- launch ----------------
extern "C" void kernel_launch(void* const* d_in, const int* in_sizes, int n_in,
                              void* d_out, int out_size)
{
    const float* latent_z = (const float*)d_in[0];
    const float* latent_f = (const float*)d_in[1];
    const float* cano     = (const float*)d_in[2];
    const float* m1_w_in  = (const float*)d_in[3];
    const float* m1_b_in  = (const float*)d_in[4];
    const float* m1_w_hid = (const float*)d_in[5];
    const float* m1_b_hid = (const float*)d_in[6];
    const float* m1_w_out = (const float*)d_in[7];
    const float* m1_b_out = (const float*)d_in[8];
    const float* m2_w_in  = (const float*)d_in[9];
    const float* m2_b_in  = (const float*)d_in[10];
    const float* m2_w_hid = (const float*)d_in[11];
    const float* m2_b_hid = (const float*)d_in[12];
    const float* m2_w_out = (const float*)d_in[13];
    const float* m2_b_out = (const float*)d_in[14];
    const float* cw_in    = (const float*)d_in[15];
    const float* cb_in    = (const float*)d_in[16];
    const float* cw_hid   = (const float*)d_in[17];
    const float* cb_hid   = (const float*)d_in[18];
    const float* cw_out   = (const float*)d_in[19];
    const float* cb_out   = (const float*)d_in[20];
    const int*   gs_part  = (const int*)d_in[21];
    const int*   uv_idx   = (const int*)d_in[22];
    float* out = (float*)d_out;

    // __device__ symbols must be resolved to true device addresses for host-side
    // argument passing (host shadow address is silently dereferenceable via ATS).
    float *hA, *hB, *attrs, *uvmap, *fA, *fB;
    cudaGetSymbolAddress((void**)&hA,    d_hA);
    cudaGetSymbolAddress((void**)&hB,    d_hB);
    cudaGetSymbolAddress((void**)&attrs, d_attrs);
    cudaGetSymbolAddress((void**)&uvmap, d_uvmap);
    cudaGetSymbolAddress((void**)&fA,    d_fA);
    cudaGetSymbolAddress((void**)&fB,    d_fB);

    // part bucketing + uvmap zeroing
    k_init<<<1, 256>>>();
    k_count<<<(G + 255) / 256, 256>>>(gs_part);
    k_offsets<<<1, 1>>>();
    k_scatter<<<(G + 255) / 256, 256>>>(gs_part);
    k_zero_uv<<<(HD * NPIX + 255) / 256, 256>>>();

    dim3 mg(625, PP);       // 625*64 = 40000 worst-case tiles per part
    dim3 sg(313, PP);       // 313*128 >= 40000

    // MLP1: 96 -> 128 -> 128 -> 128 -> 11
    k_mlp<96, MODE_X1, true><<<mg, 256>>>(nullptr, m1_w_in, 96 * 128, m1_b_in, 128,
                                          hA, latent_f, latent_z, nullptr, nullptr);
    k_mlp<128, MODE_H, true><<<mg, 256>>>(hA, m1_w_hid, 2 * 128 * 128, m1_b_hid, 2 * 128,
                                          hB, latent_f, latent_z, nullptr, nullptr);
    k_mlp<128, MODE_H, true><<<mg, 256>>>(hB, m1_w_hid + 128 * 128, 2 * 128 * 128,
                                          m1_b_hid + 128, 2 * 128,
                                          hA, latent_f, latent_z, nullptr, nullptr);
    k_mlp_small<11, false><<<sg, 256>>>(hA, m1_w_out, 128 * 11, m1_b_out, 11,
                                        attrs, nullptr);

    // MLP2: 110 -> 128 -> 128 -> 128 -> 32, scatter into uvmap
    k_mlp<110, MODE_X2, true><<<mg, 256>>>(nullptr, m2_w_in, 110 * 128, m2_b_in, 128,
                                           hB, latent_f, latent_z, cano, attrs);
    k_mlp<128, MODE_H, true><<<mg, 256>>>(hB, m2_w_hid, 2 * 128 * 128, m2_b_hid, 2 * 128,
                                          hA, latent_f, latent_z, nullptr, nullptr);
    k_mlp<128, MODE_H, true><<<mg, 256>>>(hA, m2_w_hid + 128 * 128, 2 * 128 * 128,
                                          m2_b_hid + 128, 2 * 128,
                                          hB, latent_f, latent_z, nullptr, nullptr);
    k_mlp_small<32, true><<<sg, 256>>>(hB, m2_w_out, 128 * 32, m2_b_out, 32,
                                       nullptr, uv_idx);

    // CNN: conv_in -> [relu, conv, IN] x3 -> conv_out(IN input) -> sigmoid
    dim3 cg(16, 16);
    k_conv64<HD, 0, false><<<cg, 128>>>(uvmap, cw_in, cb_in, fA);
    k_conv64<CC, 1, true><<<cg, 128>>>(fA, cw_hid, cb_hid, fB);
    k_finalize<<<1, 64>>>();
    k_conv64<CC, 2, true><<<cg, 128>>>(fB, cw_hid + 64 * 64 * 9, cb_hid + 64, fA);
    k_finalize<<<1, 64>>>();
    k_conv64<CC, 2, true><<<cg, 128>>>(fA, cw_hid + 2 * 64 * 64 * 9, cb_hid + 128, fB);
    k_finalize<<<1, 64>>>();
    k_conv_small<CC, 3, 3, true><<<cg, 256>>>(fB, cw_out, cb_out, out);
}